// round 15
// baseline (speedup 1.0000x reference)
#include <cuda_runtime.h>
#include <cuda_fp16.h>
#include <math.h>
#include <stdint.h>

typedef unsigned long long ull;

#define MAXB 32
#define MAXL 4096
#define MAXC 512
#define MAXF 2048
#define MAXNH 8
#define MAXM (MAXB * MAXL)
#define MAXCHUNK 64

// ---- scratch (static device globals; no allocation anywhere) ----
__device__ __align__(16) float  g_t[(size_t)(MAXM + 128) * MAXC];
__device__ __align__(16) __half g_memh[(size_t)MAXM * MAXC];
__device__ __align__(16) __half g_wh[MAXC * MAXC];
__device__ __align__(16) float g_qn[MAXB * MAXC];
__device__ __align__(16) float g_q[MAXB * MAXC];
__device__ __align__(16) float g_u[MAXB * MAXNH * MAXC];
__device__ __align__(16) float g_qbk[MAXB * MAXNH];
__device__ __align__(16) float g_wpart[(size_t)MAXB * MAXCHUNK * MAXNH * MAXC];
__device__ __align__(16) float g_sapart[MAXB * MAXCHUNK * MAXNH];
__device__ __align__(16) float g_w[MAXB * MAXNH * MAXC];
__device__ __align__(16) float g_sa[MAXB * MAXNH];
__device__ __align__(16) float g_x[MAXB * MAXC];
__device__ __align__(16) float g_xln[MAXB * MAXC];
__device__ __align__(16) float g_hdn[MAXB * MAXF];

// =================== helpers ===================
__device__ __forceinline__ uint32_t smem_u32(const void* p) {
    uint32_t a;
    asm("{ .reg .u64 t; cvta.to.shared.u64 t, %1; cvt.u32.u64 %0, t; }" : "=r"(a) : "l"(p));
    return a;
}
__device__ __forceinline__ void cp_async16(uint32_t dst, const void* src) {
    asm volatile("cp.async.cg.shared.global [%0], [%1], 16;" :: "r"(dst), "l"(src));
}
__device__ __forceinline__ void ldsm_x4(uint32_t* r, uint32_t addr) {
    asm volatile("ldmatrix.sync.aligned.m8n8.x4.shared.b16 {%0,%1,%2,%3}, [%4];"
                 : "=r"(r[0]), "=r"(r[1]), "=r"(r[2]), "=r"(r[3]) : "r"(addr));
}
__device__ __forceinline__ void ldsm_x4_t(uint32_t* r, uint32_t addr) {
    asm volatile("ldmatrix.sync.aligned.m8n8.x4.trans.shared.b16 {%0,%1,%2,%3}, [%4];"
                 : "=r"(r[0]), "=r"(r[1]), "=r"(r[2]), "=r"(r[3]) : "r"(addr));
}
__device__ __forceinline__ void mma16816(float* d, const uint32_t* a, const uint32_t* b) {
    asm volatile("mma.sync.aligned.m16n8k16.row.col.f32.f16.f16.f32 "
                 "{%0,%1,%2,%3}, {%4,%5,%6,%7}, {%8,%9}, {%0,%1,%2,%3};"
                 : "+f"(d[0]), "+f"(d[1]), "+f"(d[2]), "+f"(d[3])
                 : "r"(a[0]), "r"(a[1]), "r"(a[2]), "r"(a[3]), "r"(b[0]), "r"(b[1]));
}
__device__ __forceinline__ ull pack2(float x, float y) {
    ull r; asm("mov.b64 %0, {%1,%2};" : "=l"(r) : "f"(x), "f"(y)); return r;
}
__device__ __forceinline__ float2 unpack2(ull v) {
    float2 r; asm("mov.b64 {%0,%1}, %2;" : "=f"(r.x), "=f"(r.y) : "l"(v)); return r;
}
__device__ __forceinline__ ull ffma2(ull a, ull b, ull c) {
    ull d; asm("fma.rn.f32x2 %0, %1, %2, %3;" : "=l"(d) : "l"(a), "l"(b), "l"(c)); return d;
}

// merged f32->f16 conversion of two buffers in one launch
__global__ void k_cvt2(const float* __restrict__ s1, __half* __restrict__ d1, int n1,
                       const float* __restrict__ s2, __half* __restrict__ d2, int n2) {
    int i = (blockIdx.x * blockDim.x + threadIdx.x) * 4;
    const float* s; __half* d; int off;
    if (i < n1) { s = s1; d = d1; off = i; }
    else { off = i - n1; if (off >= n2) return; s = s2; d = d2; }
    float4 v = *(const float4*)(s + off);
    __half2* dp = (__half2*)(d + off);
    dp[0] = __floats2half2_rn(v.x, v.y);
    dp[1] = __floats2half2_rn(v.z, v.w);
}

// =================== Phase 1: fp16 cp.async GEMM, 3-stage pipeline @ 2 CTAs/SM ===================
// Block 128x128, BK=64, 8 warps (2x4), warp tile 64x32 (proven shape).
// 3 smem stages (96KB/CTA, 192KB for 2 CTAs): two load-groups stay in flight,
// so wait_group 2 returns ~immediately and the sync bubble shrinks.
#define GSTAGE_BYTES 32768
#define GEMM_SMEM (3 * GSTAGE_BYTES)

__global__ void __launch_bounds__(256, 2)
k_gemm_fp16(const __half* __restrict__ A, const __half* __restrict__ B,
            float* __restrict__ T, int M, int K, int N) {
    extern __shared__ __align__(1024) char smem[];
    uint32_t sbase = smem_u32(smem);
    int tid = threadIdx.x, lane = tid & 31, warp = tid >> 5;
    int n0 = blockIdx.x * 128, m0 = blockIdx.y * 128;
    int wm = warp >> 2, wn = warp & 3;
    int mw = wm * 64, nw = wn * 32;
    int nch = K / 64;

    float acc[4][4][4];
    #pragma unroll
    for (int i = 0; i < 4; i++)
        #pragma unroll
        for (int j = 0; j < 4; j++)
            #pragma unroll
            for (int e = 0; e < 4; e++) acc[i][j][e] = 0.f;

    auto issue_load = [&](int c, int stg) {
        int kc = c * 64;
        uint32_t st = sbase + stg * GSTAGE_BYTES;
        #pragma unroll
        for (int i = 0; i < 4; i++) {
            int r = (tid >> 3) + i * 32;
            int ck = tid & 7;
            uint32_t dst = st + r * 128 + ((ck ^ (r & 7)) << 4);
            cp_async16(dst, A + (size_t)(m0 + r) * K + kc + ck * 8);
        }
        #pragma unroll
        for (int i = 0; i < 4; i++) {
            int kr = (tid >> 4) + i * 16;
            int cn = tid & 15;
            uint32_t dst = st + 16384 + kr * 256 + ((cn ^ (kr & 7)) << 4);
            cp_async16(dst, B + (size_t)(kc + kr) * N + n0 + cn * 8);
        }
        asm volatile("cp.async.commit_group;" ::: "memory");
    };

    issue_load(0, 0);
    if (nch > 1) issue_load(1, 1);
    int stg = 0;
    for (int c = 0; c < nch; c++) {
        if (c + 2 < nch) {
            issue_load(c + 2, (stg + 2) % 3);
            asm volatile("cp.async.wait_group 2;" ::: "memory");
        } else if (c + 1 < nch) {
            asm volatile("cp.async.wait_group 1;" ::: "memory");
        } else {
            asm volatile("cp.async.wait_group 0;" ::: "memory");
        }
        __syncthreads();
        uint32_t st = sbase + stg * GSTAGE_BYTES;
        #pragma unroll
        for (int ks = 0; ks < 4; ks++) {
            uint32_t a[4][4];
            #pragma unroll
            for (int mf = 0; mf < 4; mf++) {
                int r = mw + mf * 16 + (lane & 15);
                int ck = ks * 2 + (lane >> 4);
                ldsm_x4(a[mf], st + r * 128 + ((ck ^ (r & 7)) << 4));
            }
            uint32_t b[4][2];
            #pragma unroll
            for (int g = 0; g < 2; g++) {
                int kr = ks * 16 + (lane & 15);
                int cn = ((nw + g * 16) >> 3) + (lane >> 4);
                uint32_t r4[4];
                ldsm_x4_t(r4, st + 16384 + kr * 256 + ((cn ^ (kr & 7)) << 4));
                b[g * 2 + 0][0] = r4[0]; b[g * 2 + 0][1] = r4[1];
                b[g * 2 + 1][0] = r4[2]; b[g * 2 + 1][1] = r4[3];
            }
            #pragma unroll
            for (int mf = 0; mf < 4; mf++)
                #pragma unroll
                for (int nf = 0; nf < 4; nf++)
                    mma16816(acc[mf][nf], a[mf], b[nf]);
        }
        __syncthreads();
        stg = (stg + 1) % 3;
    }

    int r = lane >> 2, cg = (lane & 3) * 2;
    #pragma unroll
    for (int mf = 0; mf < 4; mf++) {
        #pragma unroll
        for (int nf = 0; nf < 4; nf++) {
            float* d0 = T + (size_t)(m0 + mw + mf * 16 + r) * N + n0 + nw + nf * 8 + cg;
            *(float2*)d0 = make_float2(acc[mf][nf][0], acc[mf][nf][1]);
            *(float2*)(d0 + 8 * (size_t)N) = make_float2(acc[mf][nf][2], acc[mf][nf][3]);
        }
    }
}

// =================== K-split GEMV ===================
__global__ void __launch_bounds__(256) k_matv(
    const float* __restrict__ A, const float* __restrict__ W,
    const float* __restrict__ bias, const float* __restrict__ resid,
    float* __restrict__ dst, int Cin, int Cout, int gelu) {
    __shared__ float a_s[MAXF];
    __shared__ float part[8][32];
    int b = blockIdx.x;
    int tid = threadIdx.x, jj = tid & 31, ks = tid >> 5;
    for (int c = tid; c < Cin; c += 256) a_s[c] = A[(size_t)b * Cin + c];
    __syncthreads();
    int j = blockIdx.y * 32 + jj;
    int cpk = Cin >> 3;
    int c0 = ks * cpk;
    const float* wp = W + j;
    float a0 = 0.f, a1 = 0.f, a2 = 0.f, a3 = 0.f;
    for (int c = c0; c < c0 + cpk; c += 4) {
        a0 = fmaf(a_s[c + 0], wp[(size_t)(c + 0) * Cout], a0);
        a1 = fmaf(a_s[c + 1], wp[(size_t)(c + 1) * Cout], a1);
        a2 = fmaf(a_s[c + 2], wp[(size_t)(c + 2) * Cout], a2);
        a3 = fmaf(a_s[c + 3], wp[(size_t)(c + 3) * Cout], a3);
    }
    part[ks][jj] = (a0 + a1) + (a2 + a3);
    __syncthreads();
    if (ks == 0) {
        float acc = bias[j];
        #pragma unroll
        for (int k = 0; k < 8; k++) acc += part[k][jj];
        if (gelu) acc = 0.5f * acc * (1.f + erff(acc * 0.70710678118654752f));
        if (resid) acc += resid[(size_t)b * Cout + j];
        dst[(size_t)b * Cout + j] = acc;
    }
}

__global__ void __launch_bounds__(256) k_xv(
    const float* __restrict__ w, const float* __restrict__ sa,
    const float* __restrict__ Wkv, const float* __restrict__ bkv,
    const float* __restrict__ query, float* __restrict__ x,
    int C, int NH, int HD, int twoC) {
    __shared__ float wh_s[MAXC];
    __shared__ float part[8][32];
    int b = blockIdx.x;
    int tid = threadIdx.x, jj = tid & 31, ks = tid >> 5;
    int j = blockIdx.y * 32 + jj;
    int h = (blockIdx.y * 32) / HD;
    for (int c = tid; c < C; c += 256) wh_s[c] = w[(size_t)b * NH * C + h * C + c];
    __syncthreads();
    int cpk = C >> 3;
    int c0 = ks * cpk;
    const float* wk = Wkv + C + j;
    float a0 = 0.f, a1 = 0.f, a2 = 0.f, a3 = 0.f;
    for (int c = c0; c < c0 + cpk; c += 4) {
        a0 = fmaf(wh_s[c + 0], wk[(size_t)(c + 0) * twoC], a0);
        a1 = fmaf(wh_s[c + 1], wk[(size_t)(c + 1) * twoC], a1);
        a2 = fmaf(wh_s[c + 2], wk[(size_t)(c + 2) * twoC], a2);
        a3 = fmaf(wh_s[c + 3], wk[(size_t)(c + 3) * twoC], a3);
    }
    part[ks][jj] = (a0 + a1) + (a2 + a3);
    __syncthreads();
    if (ks == 0) {
        float acc = sa[b * NH + h] * bkv[C + j];
        #pragma unroll
        for (int k = 0; k < 8; k++) acc += part[k][jj];
        x[(size_t)b * C + j] = acc + query[(size_t)b * C + j];
    }
}

__global__ void k_rowln(const float* __restrict__ src, const float* __restrict__ gam,
                        const float* __restrict__ bet, float* __restrict__ dst, int C) {
    int row = blockIdx.x;
    const float* s = src + (size_t)row * C;
    float* d = dst + (size_t)row * C;
    int tid = threadIdx.x, lane = tid & 31, warp = tid >> 5;
    float sum = 0.f, sq = 0.f;
    for (int c = tid; c < C; c += blockDim.x) { float v = s[c]; sum += v; sq += v * v; }
    __shared__ float ra[8], rb[8], stat[2];
    #pragma unroll
    for (int o = 16; o; o >>= 1) {
        sum += __shfl_down_sync(0xffffffffu, sum, o);
        sq  += __shfl_down_sync(0xffffffffu, sq, o);
    }
    if (!lane) { ra[warp] = sum; rb[warp] = sq; }
    __syncthreads();
    if (tid == 0) {
        float S = 0.f, Q = 0.f;
        int nw = blockDim.x >> 5;
        for (int w = 0; w < nw; w++) { S += ra[w]; Q += rb[w]; }
        float mean = S / C;
        float var = Q / C - mean * mean;
        stat[0] = mean; stat[1] = rsqrtf(var + 1e-5f);
    }
    __syncthreads();
    float mean = stat[0], rstd = stat[1];
    for (int c = tid; c < C; c += blockDim.x)
        d[c] = (s[c] - mean) * rstd * gam[c] + bet[c];
}

__global__ void k_u(const float* __restrict__ q, const float* __restrict__ Wkv,
                    float* __restrict__ u, int C, int NH, int HD, int twoC, int total) {
    int gwid = (blockIdx.x * blockDim.x + threadIdx.x) >> 5;
    int lane = threadIdx.x & 31;
    if (gwid >= total) return;
    int c = gwid % C;
    int h = (gwid / C) % NH;
    int b = gwid / (C * NH);
    const float* qp = q + (size_t)b * C + h * HD;
    const float* wp = Wkv + (size_t)c * twoC + h * HD;
    float acc = 0.f;
    for (int d = lane; d < HD; d += 32) acc += qp[d] * wp[d];
    #pragma unroll
    for (int o = 16; o; o >>= 1) acc += __shfl_down_sync(0xffffffffu, acc, o);
    if (!lane) u[gwid] = acc;
}

__global__ void k_qbk(const float* __restrict__ q, const float* __restrict__ bkv,
                      float* __restrict__ qbk, int Bn, int C, int NH, int HD) {
    int idx = blockIdx.x * blockDim.x + threadIdx.x;
    if (idx >= Bn * NH) return;
    int b = idx / NH, h = idx % NH;
    float acc = 0.f;
    for (int d = 0; d < HD; d++) acc += q[(size_t)b * C + h * HD + d] * bkv[h * HD + d];
    qbk[idx] = acc;
}

// ---------------------------------------------------------------
// Phase 2: warp-per-row LN + logits, f32x2 packed math, 4 CTAs/SM (R14-proven)
// ---------------------------------------------------------------
__global__ void __launch_bounds__(256, 4) k_attn2(
    const float* __restrict__ t, const float* __restrict__ b_in,
    const float* __restrict__ g_in, const float* __restrict__ be_in,
    const float* __restrict__ u, const float* __restrict__ qbk,
    const float* __restrict__ ior, float* __restrict__ wpart, float* __restrict__ sapart,
    int L, float scale, int rpc, int nchunks) {
    __shared__ __align__(16) float u_s[8 * 512];
    __shared__ __align__(16) float stage[8][512];
    __shared__ float2 attn_st[8][8];
    __shared__ float qbk_s[8];
    __shared__ float bias_s[512], gam_s[512], bet_s[512];
    __shared__ float sa_sh[8][8];

    int b = blockIdx.y, chunk = blockIdx.x;
    int tid = threadIdx.x, lane = tid & 31, warp = tid >> 5;

    for (int i = tid; i < 4096; i += 256) u_s[i] = u[(size_t)b * 4096 + i];
    for (int i = tid; i < 512; i += 256) {
        bias_s[i] = b_in[i]; gam_s[i] = g_in[i]; bet_s[i] = be_in[i];
    }
    if (tid < 8) qbk_s[tid] = qbk[b * 8 + tid];

    ull w2[8];
    float sa_w[8];
    #pragma unroll
    for (int h = 0; h < 8; h++) { w2[h] = 0ull; sa_w[h] = 0.f; }
    int c0 = tid * 2;
    __syncthreads();

    int l0 = chunk * rpc;
    for (int pass = 0; pass < rpc / 8; pass++) {
        int l = l0 + pass * 8 + warp;
        const float* trow = t + ((size_t)b * L + l) * 512;
        float v[4][4];
        float sum = 0.f, sq = 0.f;
        #pragma unroll
        for (int k = 0; k < 4; k++) {
            int idx = k * 128 + lane * 4;
            float4 f = *(const float4*)(trow + idx);
            v[k][0] = fmaxf(f.x + bias_s[idx + 0], 0.f);
            v[k][1] = fmaxf(f.y + bias_s[idx + 1], 0.f);
            v[k][2] = fmaxf(f.z + bias_s[idx + 2], 0.f);
            v[k][3] = fmaxf(f.w + bias_s[idx + 3], 0.f);
            #pragma unroll
            for (int j = 0; j < 4; j++) { sum += v[k][j]; sq += v[k][j] * v[k][j]; }
        }
        #pragma unroll
        for (int o = 16; o; o >>= 1) {
            sum += __shfl_xor_sync(0xffffffffu, sum, o);
            sq  += __shfl_xor_sync(0xffffffffu, sq, o);
        }
        float mean = sum * (1.f / 512.f);
        float rstd = rsqrtf(sq * (1.f / 512.f) - mean * mean + 1e-5f);
        ull vp[8];
        #pragma unroll
        for (int k = 0; k < 4; k++) {
            int idx = k * 128 + lane * 4;
            #pragma unroll
            for (int j = 0; j < 4; j++)
                v[k][j] = (v[k][j] - mean) * rstd * gam_s[idx + j] + bet_s[idx + j];
            *(float4*)&stage[warp][idx] = make_float4(v[k][0], v[k][1], v[k][2], v[k][3]);
            vp[2 * k]     = pack2(v[k][0], v[k][1]);
            vp[2 * k + 1] = pack2(v[k][2], v[k][3]);
        }
        #pragma unroll
        for (int h = 0; h < 8; h++) {
            ull d2 = 0ull;
            #pragma unroll
            for (int k = 0; k < 4; k++) {
                const ulonglong2 uu = *(const ulonglong2*)&u_s[h * 512 + k * 128 + lane * 4];
                d2 = ffma2(vp[2 * k], uu.x, d2);
                d2 = ffma2(vp[2 * k + 1], uu.y, d2);
            }
            float2 dd = unpack2(d2);
            float d = dd.x + dd.y;
            #pragma unroll
            for (int o = 16; o; o >>= 1) d += __shfl_xor_sync(0xffffffffu, d, o);
            float a = (d + qbk_s[h]) * scale * ior[((size_t)(b * 8 + h)) * L + l];
            if (lane == 0) { attn_st[warp][h] = make_float2(a, a); sa_w[h] += a; }
        }
        __syncthreads();
        ull mp[8];
        #pragma unroll
        for (int r = 0; r < 8; r++) mp[r] = *(const ull*)&stage[r][c0];
        #pragma unroll
        for (int h = 0; h < 8; h++) {
            #pragma unroll
            for (int r = 0; r < 8; r++) {
                ull a2 = *(const ull*)&attn_st[r][h];
                w2[h] = ffma2(a2, mp[r], w2[h]);
            }
        }
        __syncthreads();
    }
    size_t base = ((size_t)b * nchunks + chunk) * 4096;
    #pragma unroll
    for (int h = 0; h < 8; h++) {
        float2 ww = unpack2(w2[h]);
        *(float2*)&wpart[base + h * 512 + c0] = ww;
    }
    if (lane == 0)
        #pragma unroll
        for (int h = 0; h < 8; h++) sa_sh[warp][h] = sa_w[h];
    __syncthreads();
    if (tid < 8) {
        float s = 0.f;
        #pragma unroll
        for (int w = 0; w < 8; w++) s += sa_sh[w][tid];
        sapart[((size_t)b * nchunks + chunk) * 8 + tid] = s;
    }
}

__global__ void k_reduce(const float* __restrict__ wpart, const float* __restrict__ sapart,
                         float* __restrict__ w, float* __restrict__ sa,
                         int Bn, int nchunks, int NHC, int NH) {
    int idx = blockIdx.x * blockDim.x + threadIdx.x;
    if (idx < Bn * NHC) {
        int b = idx / NHC, i = idx % NHC;
        float acc = 0.f;
        for (int ch = 0; ch < nchunks; ch++)
            acc += wpart[((size_t)b * nchunks + ch) * NHC + i];
        w[idx] = acc;
    }
    if (idx < Bn * NH) {
        int b = idx / NH, h = idx % NH;
        float acc = 0.f;
        for (int ch = 0; ch < nchunks; ch++)
            acc += sapart[((size_t)b * nchunks + ch) * NH + h];
        sa[idx] = acc;
    }
}

// ---------------------------------------------------------------
extern "C" void kernel_launch(void* const* d_in, const int* in_sizes, int n_in,
                              void* d_out, int out_size) {
    const float* query = (const float*)d_in[0];
    const float* mem   = (const float*)d_in[1];
    const float* ior   = (const float*)d_in[2];
    const float* W_in  = (const float*)d_in[3];
    const float* b_in  = (const float*)d_in[4];
    const float* g_in  = (const float*)d_in[5];
    const float* be_in = (const float*)d_in[6];
    const float* Wq    = (const float*)d_in[7];
    const float* bq    = (const float*)d_in[8];
    const float* Wkv   = (const float*)d_in[9];
    const float* bkv   = (const float*)d_in[10];
    const float* W1    = (const float*)d_in[11];
    const float* b1    = (const float*)d_in[12];
    const float* W2    = (const float*)d_in[13];
    const float* b2    = (const float*)d_in[14];
    const float* gq    = (const float*)d_in[15];
    const float* beq   = (const float*)d_in[16];
    const float* gf    = (const float*)d_in[17];
    const float* bef   = (const float*)d_in[18];

    int C  = in_sizes[4];
    int F  = in_sizes[12];
    int Bn = in_sizes[0] / C;
    int L  = in_sizes[1] / (Bn * C);
    int NH = in_sizes[2] / (Bn * L);
    int HD = C / NH;
    int M  = Bn * L;
    float scale = 1.0f / sqrtf((float)HD);

    float *p_t, *p_qn, *p_q, *p_u, *p_qbk, *p_wpart, *p_sapart, *p_w, *p_sa, *p_x, *p_xln, *p_hdn;
    __half *p_memh, *p_wh;
    cudaGetSymbolAddress((void**)&p_t, g_t);
    cudaGetSymbolAddress((void**)&p_memh, g_memh);
    cudaGetSymbolAddress((void**)&p_wh, g_wh);
    cudaGetSymbolAddress((void**)&p_qn, g_qn);
    cudaGetSymbolAddress((void**)&p_q, g_q);
    cudaGetSymbolAddress((void**)&p_u, g_u);
    cudaGetSymbolAddress((void**)&p_qbk, g_qbk);
    cudaGetSymbolAddress((void**)&p_wpart, g_wpart);
    cudaGetSymbolAddress((void**)&p_sapart, g_sapart);
    cudaGetSymbolAddress((void**)&p_w, g_w);
    cudaGetSymbolAddress((void**)&p_sa, g_sa);
    cudaGetSymbolAddress((void**)&p_x, g_x);
    cudaGetSymbolAddress((void**)&p_xln, g_xln);
    cudaGetSymbolAddress((void**)&p_hdn, g_hdn);

    cudaFuncSetAttribute(k_gemm_fp16, cudaFuncAttributeMaxDynamicSharedMemorySize, GEMM_SMEM);

    // 1: merged conversion (mem + W_in -> fp16)
    {
        int n1 = M * C, n2 = C * C;
        k_cvt2<<<((n1 + n2) / 4 + 255) / 256, 256>>>(mem, p_memh, n1, W_in, p_wh, n2);
    }
    // 2: q LN
    k_rowln<<<Bn, 256>>>(query, gq, beq, p_qn, C);
    // 3: q projection (k-split GEMV)
    {
        dim3 g(Bn, C / 32);
        k_matv<<<g, 256>>>(p_qn, Wq, bq, nullptr, p_q, C, C, 0);
    }
    // 4: big GEMM (profiled slot) — 3-stage pipeline, 2 CTAs/SM
    {
        dim3 g(C / 128, (M + 127) / 128);
        k_gemm_fp16<<<g, 256, GEMM_SMEM>>>(p_memh, p_wh, p_t, M, C, C);
    }
    // 5: qbk
    k_qbk<<<(Bn * NH + 255) / 256, 256>>>(p_q, bkv, p_qbk, Bn, C, NH, HD);
    // 6: u
    {
        int totalWarps = Bn * NH * C;
        long long threads = (long long)totalWarps * 32;
        k_u<<<(unsigned)((threads + 255) / 256), 256>>>(p_q, Wkv, p_u, C, NH, HD, 2 * C, totalWarps);
    }
    // 7: fused attn — 4 CTAs/SM
    int rpc = 128;
    int nchunks = (L + rpc - 1) / rpc;
    {
        dim3 g(nchunks, Bn);
        k_attn2<<<g, 256>>>(p_t, b_in, g_in, be_in, p_u, p_qbk, ior,
                            p_wpart, p_sapart, L, scale, rpc, nchunks);
    }
    // 8: reduce partials
    k_reduce<<<(Bn * NH * C + 255) / 256, 256>>>(p_wpart, p_sapart, p_w, p_sa,
                                                 Bn, nchunks, NH * C, NH);
    // 9: x (k-split)
    {
        dim3 g(Bn, C / 32);
        k_xv<<<g, 256>>>(p_w, p_sa, Wkv, bkv, query, p_x, C, NH, HD, 2 * C);
    }
    // 10-12: FFN
    k_rowln<<<Bn, 256>>>(p_x, gf, bef, p_xln, C);
    {
        dim3 g(Bn, F / 32);
        k_matv<<<g, 256>>>(p_xln, W1, b1, nullptr, p_hdn, C, F, 1);
    }
    {
        dim3 g(Bn, C / 32);
        k_matv<<<g, 256>>>(p_hdn, W2, b2, p_x, (float*)d_out, F, C, 0);
    }
}

// round 16
// speedup vs baseline: 1.4684x; 1.4684x over previous
#include <cuda_runtime.h>
#include <cuda_fp16.h>
#include <math.h>
#include <stdint.h>

typedef unsigned long long ull;

#define MAXB 32
#define MAXL 4096
#define MAXC 512
#define MAXF 2048
#define MAXNH 8
#define MAXM (MAXB * MAXL)
#define MAXCHUNK 64

// ---- scratch (static device globals; no allocation anywhere) ----
__device__ __align__(16) float  g_t[(size_t)(MAXM + 128) * MAXC];
__device__ __align__(16) __half g_memh[(size_t)MAXM * MAXC];
__device__ __align__(16) __half g_wh[MAXC * MAXC];
__device__ __align__(16) float g_q[MAXB * MAXC];
__device__ __align__(16) float g_u[MAXB * MAXNH * MAXC];
__device__ __align__(16) float g_qbk[MAXB * MAXNH];
__device__ __align__(16) float g_wpart[(size_t)MAXB * MAXCHUNK * MAXNH * MAXC];
__device__ __align__(16) float g_sapart[MAXB * MAXCHUNK * MAXNH];
__device__ __align__(16) float g_w[MAXB * MAXNH * MAXC];
__device__ __align__(16) float g_sa[MAXB * MAXNH];
__device__ __align__(16) float g_x[MAXB * MAXC];
__device__ __align__(16) float g_hdn[MAXB * MAXF];

// =================== helpers ===================
__device__ __forceinline__ uint32_t smem_u32(const void* p) {
    uint32_t a;
    asm("{ .reg .u64 t; cvta.to.shared.u64 t, %1; cvt.u32.u64 %0, t; }" : "=r"(a) : "l"(p));
    return a;
}
__device__ __forceinline__ void cp_async16(uint32_t dst, const void* src) {
    asm volatile("cp.async.cg.shared.global [%0], [%1], 16;" :: "r"(dst), "l"(src));
}
__device__ __forceinline__ void ldsm_x4(uint32_t* r, uint32_t addr) {
    asm volatile("ldmatrix.sync.aligned.m8n8.x4.shared.b16 {%0,%1,%2,%3}, [%4];"
                 : "=r"(r[0]), "=r"(r[1]), "=r"(r[2]), "=r"(r[3]) : "r"(addr));
}
__device__ __forceinline__ void ldsm_x4_t(uint32_t* r, uint32_t addr) {
    asm volatile("ldmatrix.sync.aligned.m8n8.x4.trans.shared.b16 {%0,%1,%2,%3}, [%4];"
                 : "=r"(r[0]), "=r"(r[1]), "=r"(r[2]), "=r"(r[3]) : "r"(addr));
}
__device__ __forceinline__ void mma16816(float* d, const uint32_t* a, const uint32_t* b) {
    asm volatile("mma.sync.aligned.m16n8k16.row.col.f32.f16.f16.f32 "
                 "{%0,%1,%2,%3}, {%4,%5,%6,%7}, {%8,%9}, {%0,%1,%2,%3};"
                 : "+f"(d[0]), "+f"(d[1]), "+f"(d[2]), "+f"(d[3])
                 : "r"(a[0]), "r"(a[1]), "r"(a[2]), "r"(a[3]), "r"(b[0]), "r"(b[1]));
}
__device__ __forceinline__ ull pack2(float x, float y) {
    ull r; asm("mov.b64 %0, {%1,%2};" : "=l"(r) : "f"(x), "f"(y)); return r;
}
__device__ __forceinline__ float2 unpack2(ull v) {
    float2 r; asm("mov.b64 {%0,%1}, %2;" : "=f"(r.x), "=f"(r.y) : "l"(v)); return r;
}
__device__ __forceinline__ ull ffma2(ull a, ull b, ull c) {
    ull d; asm("fma.rn.f32x2 %0, %1, %2, %3;" : "=l"(d) : "l"(a), "l"(b), "l"(c)); return d;
}

// merged f32->f16 conversion of two buffers in one launch
__global__ void k_cvt2(const float* __restrict__ s1, __half* __restrict__ d1, int n1,
                       const float* __restrict__ s2, __half* __restrict__ d2, int n2) {
    int i = (blockIdx.x * blockDim.x + threadIdx.x) * 4;
    const float* s; __half* d; int off;
    if (i < n1) { s = s1; d = d1; off = i; }
    else { off = i - n1; if (off >= n2) return; s = s2; d = d2; }
    float4 v = *(const float4*)(s + off);
    __half2* dp = (__half2*)(d + off);
    dp[0] = __floats2half2_rn(v.x, v.y);
    dp[1] = __floats2half2_rn(v.z, v.w);
}

// =================== Phase 1: fp16 cp.async GEMM (R14-proven) @ 2 CTAs/SM ===================
#define GSTAGE_BYTES 32768
#define GEMM_SMEM (2 * GSTAGE_BYTES)

__global__ void __launch_bounds__(256, 2)
k_gemm_fp16(const __half* __restrict__ A, const __half* __restrict__ B,
            float* __restrict__ T, int M, int K, int N) {
    extern __shared__ __align__(1024) char smem[];
    uint32_t sbase = smem_u32(smem);
    int tid = threadIdx.x, lane = tid & 31, warp = tid >> 5;
    int n0 = blockIdx.x * 128, m0 = blockIdx.y * 128;
    int wm = warp >> 2, wn = warp & 3;
    int mw = wm * 64, nw = wn * 32;
    int nch = K / 64;

    float acc[4][4][4];
    #pragma unroll
    for (int i = 0; i < 4; i++)
        #pragma unroll
        for (int j = 0; j < 4; j++)
            #pragma unroll
            for (int e = 0; e < 4; e++) acc[i][j][e] = 0.f;

    auto issue_load = [&](int c) {
        int kc = c * 64;
        uint32_t st = sbase + (c & 1) * GSTAGE_BYTES;
        #pragma unroll
        for (int i = 0; i < 4; i++) {
            int r = (tid >> 3) + i * 32;
            int ck = tid & 7;
            uint32_t dst = st + r * 128 + ((ck ^ (r & 7)) << 4);
            cp_async16(dst, A + (size_t)(m0 + r) * K + kc + ck * 8);
        }
        #pragma unroll
        for (int i = 0; i < 4; i++) {
            int kr = (tid >> 4) + i * 16;
            int cn = tid & 15;
            uint32_t dst = st + 16384 + kr * 256 + ((cn ^ (kr & 7)) << 4);
            cp_async16(dst, B + (size_t)(kc + kr) * N + n0 + cn * 8);
        }
        asm volatile("cp.async.commit_group;" ::: "memory");
    };

    issue_load(0);
    for (int c = 0; c < nch; c++) {
        if (c + 1 < nch) {
            issue_load(c + 1);
            asm volatile("cp.async.wait_group 1;" ::: "memory");
        } else {
            asm volatile("cp.async.wait_group 0;" ::: "memory");
        }
        __syncthreads();
        uint32_t st = sbase + (c & 1) * GSTAGE_BYTES;
        #pragma unroll
        for (int ks = 0; ks < 4; ks++) {
            uint32_t a[4][4];
            #pragma unroll
            for (int mf = 0; mf < 4; mf++) {
                int r = mw + mf * 16 + (lane & 15);
                int ck = ks * 2 + (lane >> 4);
                ldsm_x4(a[mf], st + r * 128 + ((ck ^ (r & 7)) << 4));
            }
            uint32_t b[4][2];
            #pragma unroll
            for (int g = 0; g < 2; g++) {
                int kr = ks * 16 + (lane & 15);
                int cn = ((nw + g * 16) >> 3) + (lane >> 4);
                uint32_t r4[4];
                ldsm_x4_t(r4, st + 16384 + kr * 256 + ((cn ^ (kr & 7)) << 4));
                b[g * 2 + 0][0] = r4[0]; b[g * 2 + 0][1] = r4[1];
                b[g * 2 + 1][0] = r4[2]; b[g * 2 + 1][1] = r4[3];
            }
            #pragma unroll
            for (int mf = 0; mf < 4; mf++)
                #pragma unroll
                for (int nf = 0; nf < 4; nf++)
                    mma16816(acc[mf][nf], a[mf], b[nf]);
        }
        __syncthreads();
    }

    int r = lane >> 2, cg = (lane & 3) * 2;
    #pragma unroll
    for (int mf = 0; mf < 4; mf++) {
        #pragma unroll
        for (int nf = 0; nf < 4; nf++) {
            float* d0 = T + (size_t)(m0 + mw + mf * 16 + r) * N + n0 + nw + nf * 8 + cg;
            *(float2*)d0 = make_float2(acc[mf][nf][0], acc[mf][nf][1]);
            *(float2*)(d0 + 8 * (size_t)N) = make_float2(acc[mf][nf][2], acc[mf][nf][3]);
        }
    }
}

// =================== K-split GEMV with optional fused input LayerNorm ===================
// dst[b,j] = op(bias[j] + sum_c LN(A[b,:])[c] * W[c,j]) (+resid)
// If gam != nullptr, the input row is LayerNormed in smem first.
__global__ void __launch_bounds__(256) k_matv(
    const float* __restrict__ A, const float* __restrict__ gam, const float* __restrict__ bet,
    const float* __restrict__ W, const float* __restrict__ bias, const float* __restrict__ resid,
    float* __restrict__ dst, int Cin, int Cout, int gelu) {
    __shared__ float a_s[MAXF];
    __shared__ float part[8][32];
    __shared__ float ra[8], rb[8], stat[2];
    int b = blockIdx.x;
    int tid = threadIdx.x, jj = tid & 31, ks = tid >> 5, lane = tid & 31;
    float sum = 0.f, sq = 0.f;
    for (int c = tid; c < Cin; c += 256) {
        float v = A[(size_t)b * Cin + c];
        a_s[c] = v; sum += v; sq += v * v;
    }
    if (gam) {
        #pragma unroll
        for (int o = 16; o; o >>= 1) {
            sum += __shfl_xor_sync(0xffffffffu, sum, o);
            sq  += __shfl_xor_sync(0xffffffffu, sq, o);
        }
        if (!lane) { ra[ks] = sum; rb[ks] = sq; }
        __syncthreads();
        if (tid == 0) {
            float S = 0.f, Q = 0.f;
            #pragma unroll
            for (int w = 0; w < 8; w++) { S += ra[w]; Q += rb[w]; }
            float mean = S / Cin;
            stat[0] = mean; stat[1] = rsqrtf(Q / Cin - mean * mean + 1e-5f);
        }
        __syncthreads();
        float mean = stat[0], rstd = stat[1];
        for (int c = tid; c < Cin; c += 256)
            a_s[c] = (a_s[c] - mean) * rstd * gam[c] + bet[c];
    }
    __syncthreads();
    int j = blockIdx.y * 32 + jj;
    int cpk = Cin >> 3;
    int c0 = ks * cpk;
    const float* wp = W + j;
    float a0 = 0.f, a1 = 0.f, a2 = 0.f, a3 = 0.f;
    for (int c = c0; c < c0 + cpk; c += 4) {
        a0 = fmaf(a_s[c + 0], wp[(size_t)(c + 0) * Cout], a0);
        a1 = fmaf(a_s[c + 1], wp[(size_t)(c + 1) * Cout], a1);
        a2 = fmaf(a_s[c + 2], wp[(size_t)(c + 2) * Cout], a2);
        a3 = fmaf(a_s[c + 3], wp[(size_t)(c + 3) * Cout], a3);
    }
    part[ks][jj] = (a0 + a1) + (a2 + a3);
    __syncthreads();
    if (ks == 0) {
        float acc = bias[j];
        #pragma unroll
        for (int k = 0; k < 8; k++) acc += part[k][jj];
        if (gelu) acc = 0.5f * acc * (1.f + erff(acc * 0.70710678118654752f));
        if (resid) acc += resid[(size_t)b * Cout + j];
        dst[(size_t)b * Cout + j] = acc;
    }
}

__global__ void __launch_bounds__(256) k_xv(
    const float* __restrict__ w, const float* __restrict__ sa,
    const float* __restrict__ Wkv, const float* __restrict__ bkv,
    const float* __restrict__ query, float* __restrict__ x,
    int C, int NH, int HD, int twoC) {
    __shared__ float wh_s[MAXC];
    __shared__ float part[8][32];
    int b = blockIdx.x;
    int tid = threadIdx.x, jj = tid & 31, ks = tid >> 5;
    int j = blockIdx.y * 32 + jj;
    int h = (blockIdx.y * 32) / HD;
    for (int c = tid; c < C; c += 256) wh_s[c] = w[(size_t)b * NH * C + h * C + c];
    __syncthreads();
    int cpk = C >> 3;
    int c0 = ks * cpk;
    const float* wk = Wkv + C + j;
    float a0 = 0.f, a1 = 0.f, a2 = 0.f, a3 = 0.f;
    for (int c = c0; c < c0 + cpk; c += 4) {
        a0 = fmaf(wh_s[c + 0], wk[(size_t)(c + 0) * twoC], a0);
        a1 = fmaf(wh_s[c + 1], wk[(size_t)(c + 1) * twoC], a1);
        a2 = fmaf(wh_s[c + 2], wk[(size_t)(c + 2) * twoC], a2);
        a3 = fmaf(wh_s[c + 3], wk[(size_t)(c + 3) * twoC], a3);
    }
    part[ks][jj] = (a0 + a1) + (a2 + a3);
    __syncthreads();
    if (ks == 0) {
        float acc = sa[b * NH + h] * bkv[C + j];
        #pragma unroll
        for (int k = 0; k < 8; k++) acc += part[k][jj];
        x[(size_t)b * C + j] = acc + query[(size_t)b * C + j];
    }
}

__global__ void k_u(const float* __restrict__ q, const float* __restrict__ Wkv,
                    float* __restrict__ u, int C, int NH, int HD, int twoC, int total) {
    int gwid = (blockIdx.x * blockDim.x + threadIdx.x) >> 5;
    int lane = threadIdx.x & 31;
    if (gwid >= total) return;
    int c = gwid % C;
    int h = (gwid / C) % NH;
    int b = gwid / (C * NH);
    const float* qp = q + (size_t)b * C + h * HD;
    const float* wp = Wkv + (size_t)c * twoC + h * HD;
    float acc = 0.f;
    for (int d = lane; d < HD; d += 32) acc += qp[d] * wp[d];
    #pragma unroll
    for (int o = 16; o; o >>= 1) acc += __shfl_down_sync(0xffffffffu, acc, o);
    if (!lane) u[gwid] = acc;
}

__global__ void k_qbk(const float* __restrict__ q, const float* __restrict__ bkv,
                      float* __restrict__ qbk, int Bn, int C, int NH, int HD) {
    int idx = blockIdx.x * blockDim.x + threadIdx.x;
    if (idx >= Bn * NH) return;
    int b = idx / NH, h = idx % NH;
    float acc = 0.f;
    for (int d = 0; d < HD; d++) acc += q[(size_t)b * C + h * HD + d] * bkv[h * HD + d];
    qbk[idx] = acc;
}

// ---------------------------------------------------------------
// Phase 2: warp-per-row LN + logits, f32x2 packed math, 4 CTAs/SM (R14-proven)
// ---------------------------------------------------------------
__global__ void __launch_bounds__(256, 4) k_attn2(
    const float* __restrict__ t, const float* __restrict__ b_in,
    const float* __restrict__ g_in, const float* __restrict__ be_in,
    const float* __restrict__ u, const float* __restrict__ qbk,
    const float* __restrict__ ior, float* __restrict__ wpart, float* __restrict__ sapart,
    int L, float scale, int rpc, int nchunks) {
    __shared__ __align__(16) float u_s[8 * 512];
    __shared__ __align__(16) float stage[8][512];
    __shared__ float2 attn_st[8][8];
    __shared__ float qbk_s[8];
    __shared__ float bias_s[512], gam_s[512], bet_s[512];
    __shared__ float sa_sh[8][8];

    int b = blockIdx.y, chunk = blockIdx.x;
    int tid = threadIdx.x, lane = tid & 31, warp = tid >> 5;

    for (int i = tid; i < 4096; i += 256) u_s[i] = u[(size_t)b * 4096 + i];
    for (int i = tid; i < 512; i += 256) {
        bias_s[i] = b_in[i]; gam_s[i] = g_in[i]; bet_s[i] = be_in[i];
    }
    if (tid < 8) qbk_s[tid] = qbk[b * 8 + tid];

    ull w2[8];
    float sa_w[8];
    #pragma unroll
    for (int h = 0; h < 8; h++) { w2[h] = 0ull; sa_w[h] = 0.f; }
    int c0 = tid * 2;
    __syncthreads();

    int l0 = chunk * rpc;
    for (int pass = 0; pass < rpc / 8; pass++) {
        int l = l0 + pass * 8 + warp;
        const float* trow = t + ((size_t)b * L + l) * 512;
        float v[4][4];
        float sum = 0.f, sq = 0.f;
        #pragma unroll
        for (int k = 0; k < 4; k++) {
            int idx = k * 128 + lane * 4;
            float4 f = *(const float4*)(trow + idx);
            v[k][0] = fmaxf(f.x + bias_s[idx + 0], 0.f);
            v[k][1] = fmaxf(f.y + bias_s[idx + 1], 0.f);
            v[k][2] = fmaxf(f.z + bias_s[idx + 2], 0.f);
            v[k][3] = fmaxf(f.w + bias_s[idx + 3], 0.f);
            #pragma unroll
            for (int j = 0; j < 4; j++) { sum += v[k][j]; sq += v[k][j] * v[k][j]; }
        }
        #pragma unroll
        for (int o = 16; o; o >>= 1) {
            sum += __shfl_xor_sync(0xffffffffu, sum, o);
            sq  += __shfl_xor_sync(0xffffffffu, sq, o);
        }
        float mean = sum * (1.f / 512.f);
        float rstd = rsqrtf(sq * (1.f / 512.f) - mean * mean + 1e-5f);
        ull vp[8];
        #pragma unroll
        for (int k = 0; k < 4; k++) {
            int idx = k * 128 + lane * 4;
            #pragma unroll
            for (int j = 0; j < 4; j++)
                v[k][j] = (v[k][j] - mean) * rstd * gam_s[idx + j] + bet_s[idx + j];
            *(float4*)&stage[warp][idx] = make_float4(v[k][0], v[k][1], v[k][2], v[k][3]);
            vp[2 * k]     = pack2(v[k][0], v[k][1]);
            vp[2 * k + 1] = pack2(v[k][2], v[k][3]);
        }
        #pragma unroll
        for (int h = 0; h < 8; h++) {
            ull d2 = 0ull;
            #pragma unroll
            for (int k = 0; k < 4; k++) {
                const ulonglong2 uu = *(const ulonglong2*)&u_s[h * 512 + k * 128 + lane * 4];
                d2 = ffma2(vp[2 * k], uu.x, d2);
                d2 = ffma2(vp[2 * k + 1], uu.y, d2);
            }
            float2 dd = unpack2(d2);
            float d = dd.x + dd.y;
            #pragma unroll
            for (int o = 16; o; o >>= 1) d += __shfl_xor_sync(0xffffffffu, d, o);
            float a = (d + qbk_s[h]) * scale * ior[((size_t)(b * 8 + h)) * L + l];
            if (lane == 0) { attn_st[warp][h] = make_float2(a, a); sa_w[h] += a; }
        }
        __syncthreads();
        ull mp[8];
        #pragma unroll
        for (int r = 0; r < 8; r++) mp[r] = *(const ull*)&stage[r][c0];
        #pragma unroll
        for (int h = 0; h < 8; h++) {
            #pragma unroll
            for (int r = 0; r < 8; r++) {
                ull a2 = *(const ull*)&attn_st[r][h];
                w2[h] = ffma2(a2, mp[r], w2[h]);
            }
        }
        __syncthreads();
    }
    size_t base = ((size_t)b * nchunks + chunk) * 4096;
    #pragma unroll
    for (int h = 0; h < 8; h++) {
        float2 ww = unpack2(w2[h]);
        *(float2*)&wpart[base + h * 512 + c0] = ww;
    }
    if (lane == 0)
        #pragma unroll
        for (int h = 0; h < 8; h++) sa_sh[warp][h] = sa_w[h];
    __syncthreads();
    if (tid < 8) {
        float s = 0.f;
        #pragma unroll
        for (int w = 0; w < 8; w++) s += sa_sh[w][tid];
        sapart[((size_t)b * nchunks + chunk) * 8 + tid] = s;
    }
}

__global__ void k_reduce(const float* __restrict__ wpart, const float* __restrict__ sapart,
                         float* __restrict__ w, float* __restrict__ sa,
                         int Bn, int nchunks, int NHC, int NH) {
    int idx = blockIdx.x * blockDim.x + threadIdx.x;
    if (idx < Bn * NHC) {
        int b = idx / NHC, i = idx % NHC;
        float acc = 0.f;
        for (int ch = 0; ch < nchunks; ch++)
            acc += wpart[((size_t)b * nchunks + ch) * NHC + i];
        w[idx] = acc;
    }
    if (idx < Bn * NH) {
        int b = idx / NH, h = idx % NH;
        float acc = 0.f;
        for (int ch = 0; ch < nchunks; ch++)
            acc += sapart[((size_t)b * nchunks + ch) * NH + h];
        sa[idx] = acc;
    }
}

// ---------------------------------------------------------------
extern "C" void kernel_launch(void* const* d_in, const int* in_sizes, int n_in,
                              void* d_out, int out_size) {
    const float* query = (const float*)d_in[0];
    const float* mem   = (const float*)d_in[1];
    const float* ior   = (const float*)d_in[2];
    const float* W_in  = (const float*)d_in[3];
    const float* b_in  = (const float*)d_in[4];
    const float* g_in  = (const float*)d_in[5];
    const float* be_in = (const float*)d_in[6];
    const float* Wq    = (const float*)d_in[7];
    const float* bq    = (const float*)d_in[8];
    const float* Wkv   = (const float*)d_in[9];
    const float* bkv   = (const float*)d_in[10];
    const float* W1    = (const float*)d_in[11];
    const float* b1    = (const float*)d_in[12];
    const float* W2    = (const float*)d_in[13];
    const float* b2    = (const float*)d_in[14];
    const float* gq    = (const float*)d_in[15];
    const float* beq   = (const float*)d_in[16];
    const float* gf    = (const float*)d_in[17];
    const float* bef   = (const float*)d_in[18];

    int C  = in_sizes[4];
    int F  = in_sizes[12];
    int Bn = in_sizes[0] / C;
    int L  = in_sizes[1] / (Bn * C);
    int NH = in_sizes[2] / (Bn * L);
    int HD = C / NH;
    int M  = Bn * L;
    float scale = 1.0f / sqrtf((float)HD);

    float *p_t, *p_q, *p_u, *p_qbk, *p_wpart, *p_sapart, *p_w, *p_sa, *p_x, *p_hdn;
    __half *p_memh, *p_wh;
    cudaGetSymbolAddress((void**)&p_t, g_t);
    cudaGetSymbolAddress((void**)&p_memh, g_memh);
    cudaGetSymbolAddress((void**)&p_wh, g_wh);
    cudaGetSymbolAddress((void**)&p_q, g_q);
    cudaGetSymbolAddress((void**)&p_u, g_u);
    cudaGetSymbolAddress((void**)&p_qbk, g_qbk);
    cudaGetSymbolAddress((void**)&p_wpart, g_wpart);
    cudaGetSymbolAddress((void**)&p_sapart, g_sapart);
    cudaGetSymbolAddress((void**)&p_w, g_w);
    cudaGetSymbolAddress((void**)&p_sa, g_sa);
    cudaGetSymbolAddress((void**)&p_x, g_x);
    cudaGetSymbolAddress((void**)&p_hdn, g_hdn);

    cudaFuncSetAttribute(k_gemm_fp16, cudaFuncAttributeMaxDynamicSharedMemorySize, GEMM_SMEM);

    // 1: merged conversion (mem + W_in -> fp16)
    {
        int n1 = M * C, n2 = C * C;
        k_cvt2<<<((n1 + n2) / 4 + 255) / 256, 256>>>(mem, p_memh, n1, W_in, p_wh, n2);
    }
    // 2: q projection with fused LN
    {
        dim3 g(Bn, C / 32);
        k_matv<<<g, 256>>>(query, gq, beq, Wq, bq, nullptr, p_q, C, C, 0);
    }
    // 3: big GEMM (profiled slot) — R14-proven, 2 CTAs/SM, 2-stage
    {
        dim3 g(C / 128, (M + 127) / 128);
        k_gemm_fp16<<<g, 256, GEMM_SMEM>>>(p_memh, p_wh, p_t, M, C, C);
    }
    // 4: qbk
    k_qbk<<<(Bn * NH + 255) / 256, 256>>>(p_q, bkv, p_qbk, Bn, C, NH, HD);
    // 5: u
    {
        int totalWarps = Bn * NH * C;
        long long threads = (long long)totalWarps * 32;
        k_u<<<(unsigned)((threads + 255) / 256), 256>>>(p_q, Wkv, p_u, C, NH, HD, 2 * C, totalWarps);
    }
    // 6: fused attn — 4 CTAs/SM
    int rpc = 128;
    int nchunks = (L + rpc - 1) / rpc;
    {
        dim3 g(nchunks, Bn);
        k_attn2<<<g, 256>>>(p_t, b_in, g_in, be_in, p_u, p_qbk, ior,
                            p_wpart, p_sapart, L, scale, rpc, nchunks);
    }
    // 7: reduce partials
    k_reduce<<<(Bn * NH * C + 255) / 256, 256>>>(p_wpart, p_sapart, p_w, p_sa,
                                                 Bn, nchunks, NH * C, NH);
    // 8: x (k-split)
    {
        dim3 g(Bn, C / 32);
        k_xv<<<g, 256>>>(p_w, p_sa, Wkv, bkv, query, p_x, C, NH, HD, 2 * C);
    }
    // 9: FFN up with fused LN
    {
        dim3 g(Bn, F / 32);
        k_matv<<<g, 256>>>(p_x, gf, bef, W1, b1, nullptr, p_hdn, C, F, 1);
    }
    // 10: FFN down + residual
    {
        dim3 g(Bn, C / 32);
        k_matv<<<g, 256>>>(p_hdn, nullptr, nullptr, W2, b2, p_x, (float*)d_out, F, C, 0);
    }
}